// round 10
// baseline (speedup 1.0000x reference)
#include <cuda_runtime.h>
#include <math.h>

// ---------------------------------------------------------------------------
// SeFT network, round 9:
//  - gather: coalesced ballot compaction (k_rows + k_compact)
//  - k_mlp: smem-staged weights; NEW thread map 4 rows x 8 obs per thread ->
//    activation LDS become warp broadcasts (6 smem wavefronts / 16 FFMA2)
//  - attention: flash-style two-pass with NCHUNK=16 (128-l chunks, 512 blocks)
// ---------------------------------------------------------------------------

#define BMAX    32
#define LSTRIDE 2048
#define NCHUNK  16          // LSTRIDE / 128
#define CLEN    128         // l per chunk
#define HID     128
#define NIN     34
#define ASTR    36          // activation row stride (floats)

typedef unsigned long long ull;

__device__ float    g_St[BMAX * LSTRIDE];
__device__ float    g_Sc[BMAX * LSTRIDE];
__device__ float    g_Sx[BMAX * LSTRIDE];
__device__ int      g_lens[BMAX];
__device__ int      g_maxlen;
__device__ int      g_rowcnt[4096];
__device__ unsigned g_rowmask[4096];
__device__ float    g_rowtime[4096];
__device__ float    g_enc[(size_t)BMAX * LSTRIDE * HID];   // [b][l][e]
__device__ float    g_kT [(size_t)BMAX * HID * LSTRIDE];   // [b][e][l]
__device__ float    g_q  [BMAX * HID];
__device__ float    g_cm  [BMAX * 4 * NCHUNK];             // chunk max
__device__ float    g_csum[BMAX * 4 * NCHUNK];             // chunk expsum
__device__ float    g_part[(size_t)BMAX * NCHUNK * 512];   // [b][chunk][h*128+e]

// ---- packed fp32x2 helpers -------------------------------------------------
__device__ __forceinline__ ull pack2(float x, float y) {
    ull r;
    asm("mov.b64 %0, {%1, %2};" : "=l"(r) : "f"(x), "f"(y));
    return r;
}
__device__ __forceinline__ void unpack2(ull v, float& lo, float& hi) {
    asm("mov.b64 {%0, %1}, %2;" : "=f"(lo), "=f"(hi) : "l"(v));
}
__device__ __forceinline__ ull ffma2(ull a, ull b, ull c) {
    ull d;
    asm("fma.rn.f32x2 %0, %1, %2, %3;" : "=l"(d) : "l"(a), "l"(b), "l"(c));
    return d;
}

// ---------------------------------------------------------------------------
// Kernel 1: per-row nonzero mask/count/time. One warp per row, coalesced.
// ---------------------------------------------------------------------------
__global__ void k_rows(const float* __restrict__ times,
                       const int*   __restrict__ time_ptr,
                       const int*   __restrict__ M,
                       int R, int V, int n_times)
{
    int w = (blockIdx.x * blockDim.x + threadIdx.x) >> 5;
    int lane = threadIdx.x & 31;
    if (w >= R) return;
    int m = 0;
    if (lane < V) m = (M[w * V + lane] != 0);
    unsigned mask = __ballot_sync(0xffffffffu, m);
    if (lane == 0) {
        g_rowmask[w] = mask;
        g_rowcnt[w]  = __popc(mask);
        int lo = 0, hi = n_times - 1;
        while (lo < hi) {
            int mid = (lo + hi + 1) >> 1;
            if (time_ptr[mid] <= w) lo = mid; else hi = mid - 1;
        }
        g_rowtime[w] = times[lo];
    }
}

// ---------------------------------------------------------------------------
// Kernel 2: per-patient compaction (rows contiguous per patient).
// ---------------------------------------------------------------------------
__global__ void k_compact(const float* __restrict__ X, int R, int V, int B)
{
    int b = blockIdx.x;
    int rpp = R / B;
    int r0 = b * rpp;
    int t = threadIdx.x;

    __shared__ int ssum[256];
    __shared__ int sstart[256];
    int cnt = (t < rpp) ? g_rowcnt[r0 + t] : 0;
    ssum[t] = cnt;
    __syncthreads();
    for (int off = 1; off < 256; off <<= 1) {
        int v = (t >= off) ? ssum[t - off] : 0;
        __syncthreads();
        ssum[t] += v;
        __syncthreads();
    }
    int tot = ssum[255];
    sstart[t] = ssum[t] - cnt;
    __syncthreads();

    int lane = t & 31, w = t >> 5;
    for (int lr = w; lr < rpp; lr += 8) {
        int r = r0 + lr;
        unsigned mask = g_rowmask[r];
        float tv = g_rowtime[r];
        int start = sstart[lr];
        if (lane < V && ((mask >> lane) & 1u)) {
            int pos = start + __popc(mask & ((1u << lane) - 1u));
            if (pos < LSTRIDE) {
                g_St[b * LSTRIDE + pos] = tv;
                g_Sc[b * LSTRIDE + pos] = (float)lane;
                g_Sx[b * LSTRIDE + pos] = X[r * V + lane];
            }
        }
    }
    if (t == 0) {
        int L = min(tot, LSTRIDE);
        g_lens[b] = L;
        atomicMax(&g_maxlen, L);   // idempotent across replays
    }
}

// ---------------------------------------------------------------------------
// 128->128 dense layer, f32x2, weights staged in smem chunks of 32 k-rows.
// Thread (r = tid&31, h = tid>>5) computes output rows r, r+32, r+64, r+96
// for obs [h*8, h*8+8). Whole warp shares h -> activation LDS.128 are
// broadcasts (2 wavefronts), weight LDS consecutive-lane (4 wavefronts).
// acc[q*4+p] = row r+q*32, obs pair (h*8+2p, h*8+2p+1).
// ---------------------------------------------------------------------------
__device__ __forceinline__ void dense128(const float* __restrict__ W,
                                         const float* __restrict__ bias,
                                         const float* sIn, float* wbuf,
                                         ull acc[16], int r, int h, int tid)
{
#pragma unroll
    for (int q = 0; q < 4; q++) {
        float bb = __ldg(&bias[r + q * 32]);
        ull b2 = pack2(bb, bb);
#pragma unroll
        for (int p = 0; p < 4; p++) acc[q * 4 + p] = b2;
    }

    for (int c = 0; c < 4; c++) {
        // stage 128x32 chunk, coalesced LDG.128, conflict-free STS
        for (int i4 = tid; i4 < 1024; i4 += 128) {
            int e  = i4 << 2;        // element = o*32 + kk
            int o  = e >> 5;
            int kk = e & 31;
            float4 v = __ldg((const float4*)(W + o * HID + c * 32 + kk));
            wbuf[kk * 129 + o]       = v.x;
            wbuf[(kk + 1) * 129 + o] = v.y;
            wbuf[(kk + 2) * 129 + o] = v.z;
            wbuf[(kk + 3) * 129 + o] = v.w;
        }
        __syncthreads();
#pragma unroll 4
        for (int kk = 0; kk < 32; kk++) {
            const float* wrow = wbuf + kk * 129;
            float w0 = wrow[r], w1 = wrow[r + 32], w2 = wrow[r + 64], w3 = wrow[r + 96];
            const ulonglong2* rowp =
                (const ulonglong2*)(sIn + (c * 32 + kk) * ASTR + h * 8);
            ulonglong2 va = rowp[0], vb = rowp[1];
            ull w;
            w = pack2(w0, w0);
            acc[0]  = ffma2(va.x, w, acc[0]);  acc[1]  = ffma2(va.y, w, acc[1]);
            acc[2]  = ffma2(vb.x, w, acc[2]);  acc[3]  = ffma2(vb.y, w, acc[3]);
            w = pack2(w1, w1);
            acc[4]  = ffma2(va.x, w, acc[4]);  acc[5]  = ffma2(va.y, w, acc[5]);
            acc[6]  = ffma2(vb.x, w, acc[6]);  acc[7]  = ffma2(vb.y, w, acc[7]);
            w = pack2(w2, w2);
            acc[8]  = ffma2(va.x, w, acc[8]);  acc[9]  = ffma2(va.y, w, acc[9]);
            acc[10] = ffma2(vb.x, w, acc[10]); acc[11] = ffma2(vb.y, w, acc[11]);
            w = pack2(w3, w3);
            acc[12] = ffma2(va.x, w, acc[12]); acc[13] = ffma2(va.y, w, acc[13]);
            acc[14] = ffma2(vb.x, w, acc[14]); acc[15] = ffma2(vb.y, w, acc[15]);
        }
        __syncthreads();
    }
}

// relu epilogue into [k][obs] smem for rows r+q*32, obs [h*8, h*8+8)
__device__ __forceinline__ void epi_relu(float* dst, ull acc[16], int r, int h)
{
#pragma unroll
    for (int q = 0; q < 4; q++) {
        float* d = dst + (r + q * 32) * ASTR + h * 8;
#pragma unroll
        for (int p = 0; p < 4; p++) {
            float lo, hi;
            unpack2(acc[q * 4 + p], lo, hi);
            *(ull*)(d + 2 * p) = pack2(fmaxf(lo, 0.f), fmaxf(hi, 0.f));
        }
    }
}

// ---------------------------------------------------------------------------
// Kernel 3: fused MLP + projection, 32-obs tiles.
// Block 0 = query path (lastfeat inline, Wq -> g_q). Others: enc + kT.
//   L0: in sf, w sA, out sA      L1: in sA, w sB, out sB
//   L2: in sB, w sA, out sA+enc  Pr: in sA, w sB, out global
// ---------------------------------------------------------------------------
__global__ __launch_bounds__(128) void k_mlp(
    const float* __restrict__ W0, const float* __restrict__ b0,
    const float* __restrict__ W1, const float* __restrict__ b1,
    const float* __restrict__ W2, const float* __restrict__ b2,
    const float* __restrict__ Wk, const float* __restrict__ bk,
    const float* __restrict__ Wq, const float* __restrict__ bq,
    int B)
{
    __shared__ __align__(16) float sf[NIN * ASTR];
    __shared__ __align__(16) float sA[HID * ASTR];
    __shared__ __align__(16) float sB[HID * ASTR];

    int tid = threadIdx.x;
    int r = tid & 31;
    int h = tid >> 5;

    bool special = (blockIdx.x == 0);
    int b = 0, l0 = 0, nv = 0;
    if (!special) {
        int bi = blockIdx.x - 1;
        b = bi >> 6;
        int lt = bi & 63;
        int len = g_lens[b];
        l0 = lt * 32;
        if (l0 >= len) return;
        nv = min(32, len - l0);
    } else {
        nv = min(B, 32);
    }

    // stage W0 [128][34] into sA at stride 129 (dead until L0 epilogue)
    for (int i = tid; i < HID * NIN; i += 128) {
        int o = i / NIN, k = i - o * NIN;
        sA[k * 129 + o] = __ldg(&W0[i]);
    }

    // features into [k][obs] layout
    if (tid < 32) {
        int o = tid;
        float tv = 0.f, cv = 0.f, xv = 0.f;
        if (special) {
            int L = g_maxlen;
            if (o < nv && L >= 1 && g_lens[o] == L) {
                tv = g_St[o * LSTRIDE + L - 1];
                cv = g_Sc[o * LSTRIDE + L - 1];
                xv = g_Sx[o * LSTRIDE + L - 1];
            }
        } else if (o < nv) {
            tv = g_St[b * LSTRIDE + l0 + o];
            cv = g_Sc[b * LSTRIDE + l0 + o];
            xv = g_Sx[b * LSTRIDE + l0 + o];
        }
#pragma unroll
        for (int i = 0; i < 16; i++) {
            float ts = powf(100.0f, (float)i * (1.0f / 15.0f));
            float sn, cs;
            sincosf(tv / ts, &sn, &cs);
            sf[i * ASTR + o]        = sn;
            sf[(16 + i) * ASTR + o] = cs;
        }
        sf[32 * ASTR + o] = cv;
        sf[33 * ASTR + o] = xv;
    }
    __syncthreads();

    ull acc[16];

    // ---- layer 0: 34 -> 128, relu (weights in sA, input sf) ----
    {
#pragma unroll
        for (int q = 0; q < 4; q++) {
            float bb = __ldg(&b0[r + q * 32]);
            ull b2 = pack2(bb, bb);
#pragma unroll
            for (int p = 0; p < 4; p++) acc[q * 4 + p] = b2;
        }
#pragma unroll 2
        for (int k = 0; k < NIN; k++) {
            const float* wrow = sA + k * 129;
            float w0 = wrow[r], w1 = wrow[r + 32], w2 = wrow[r + 64], w3 = wrow[r + 96];
            const ulonglong2* rowp = (const ulonglong2*)(sf + k * ASTR + h * 8);
            ulonglong2 va = rowp[0], vb = rowp[1];
            ull w;
            w = pack2(w0, w0);
            acc[0]  = ffma2(va.x, w, acc[0]);  acc[1]  = ffma2(va.y, w, acc[1]);
            acc[2]  = ffma2(vb.x, w, acc[2]);  acc[3]  = ffma2(vb.y, w, acc[3]);
            w = pack2(w1, w1);
            acc[4]  = ffma2(va.x, w, acc[4]);  acc[5]  = ffma2(va.y, w, acc[5]);
            acc[6]  = ffma2(vb.x, w, acc[6]);  acc[7]  = ffma2(vb.y, w, acc[7]);
            w = pack2(w2, w2);
            acc[8]  = ffma2(va.x, w, acc[8]);  acc[9]  = ffma2(va.y, w, acc[9]);
            acc[10] = ffma2(vb.x, w, acc[10]); acc[11] = ffma2(vb.y, w, acc[11]);
            w = pack2(w3, w3);
            acc[12] = ffma2(va.x, w, acc[12]); acc[13] = ffma2(va.y, w, acc[13]);
            acc[14] = ffma2(vb.x, w, acc[14]); acc[15] = ffma2(vb.y, w, acc[15]);
        }
        __syncthreads();            // weights in sA dead after this
        epi_relu(sA, acc, r, h);
    }
    __syncthreads();

    // ---- layer 1: 128 -> 128, relu (in sA, weights+out sB) ----
    dense128(W1, b1, sA, sB, acc, r, h, tid);
    epi_relu(sB, acc, r, h);
    __syncthreads();

    // ---- layer 2 (enc): 128 -> 128, linear (in sB, weights+out sA) ----
    dense128(W2, b2, sB, sA, acc, r, h, tid);
    {
        float v[4][8];
#pragma unroll
        for (int q = 0; q < 4; q++)
#pragma unroll
            for (int p = 0; p < 4; p++)
                unpack2(acc[q * 4 + p], v[q][2 * p], v[q][2 * p + 1]);
#pragma unroll
        for (int q = 0; q < 4; q++) {
            float* d = sA + (r + q * 32) * ASTR + h * 8;
#pragma unroll
            for (int p = 0; p < 4; p++) *(ull*)(d + 2 * p) = acc[q * 4 + p];
        }
        if (!special) {
#pragma unroll
            for (int o = 0; o < 8; o++) {
                int og = h * 8 + o;
                if (og < nv) {
                    size_t base = ((size_t)b * LSTRIDE + l0 + og) * HID;
#pragma unroll
                    for (int q = 0; q < 4; q++)
                        g_enc[base + r + q * 32] = v[q][o];
                }
            }
        }
    }
    __syncthreads();

    // ---- projection: Wk (normal) or Wq (special); in sA, weights sB ----
    dense128(special ? Wq : Wk, special ? bq : bk, sA, sB, acc, r, h, tid);
    {
        float v[4][8];
#pragma unroll
        for (int q = 0; q < 4; q++)
#pragma unroll
            for (int p = 0; p < 4; p++)
                unpack2(acc[q * 4 + p], v[q][2 * p], v[q][2 * p + 1]);
        if (special) {
#pragma unroll
            for (int o = 0; o < 8; o++) {
                int og = h * 8 + o;
                if (og < nv) {
#pragma unroll
                    for (int q = 0; q < 4; q++)
                        g_q[og * HID + r + q * 32] = v[q][o];
                }
            }
        } else {
#pragma unroll
            for (int q = 0; q < 4; q++) {
                float* gk = g_kT + ((size_t)b * HID + r + q * 32) * LSTRIDE + l0 + h * 8;
#pragma unroll
                for (int o = 0; o < 8; o += 4) {
                    int og = h * 8 + o;
                    if (og + 4 <= nv) {
                        *(float4*)(gk + o) =
                            make_float4(v[q][o], v[q][o+1], v[q][o+2], v[q][o+3]);
                    } else {
                        for (int m = 0; m < 4; m++)
                            if (og + m < nv) gk[o + m] = v[q][o + m];
                    }
                }
            }
        }
    }
}

// ---------------------------------------------------------------------------
// Kernel 4: flash-style attention pass A. grid (B, NCHUNK), 512 threads.
// Uniform thread map t = h*128 + li for all phases (scores over l=li,
// reductions within 128-group, enc-sum over e=li).
// ---------------------------------------------------------------------------
__global__ __launch_bounds__(512) void k_attnA()
{
    int b     = blockIdx.x;
    int chunk = blockIdx.y;
    int t     = threadIdx.x;
    int len   = min(g_lens[b], LSTRIDE);
    int l0    = chunk * CLEN;

    __shared__ float sq[HID];
    __shared__ float ssc[4 * CLEN];
    __shared__ float sred[512];
    __shared__ float sm[4], ssum[4];

    if (t < HID) sq[t] = g_q[b * HID + t];
    __syncthreads();

    const float scale = 0.17677669529663687f; // 1/sqrt(32)
    int h  = t >> 7;
    int li = t & 127;

    // scores: thread (h, l = l0+li)
    float s = -1e30f;
    {
        int l = l0 + li;
        if (l < len) {
            const float* kb = g_kT + ((size_t)b * HID + h * 32) * LSTRIDE + l;
            float a0 = 0.f, a1 = 0.f;
#pragma unroll 8
            for (int e2 = 0; e2 < 32; e2 += 2) {
                a0 = fmaf(__ldg(&kb[(size_t)e2 * LSTRIDE]),       sq[h * 32 + e2],     a0);
                a1 = fmaf(__ldg(&kb[(size_t)(e2 + 1) * LSTRIDE]), sq[h * 32 + e2 + 1], a1);
            }
            s = (a0 + a1) * scale;
        }
    }

    // chunk max per head (reduce within 128-group)
    sred[t] = s;
    __syncthreads();
#pragma unroll
    for (int o = 64; o > 0; o >>= 1) {
        if (li < o) sred[t] = fmaxf(sred[t], sred[t + o]);
        __syncthreads();
    }
    if (li == 0) sm[h] = sred[t];
    __syncthreads();

    // exp weight (zero for padded l)
    float wv = (l0 + li < len) ? expf(s - sm[h]) : 0.f;
    ssc[h * CLEN + li] = wv;

    // chunk expsum per head
    sred[t] = wv;
    __syncthreads();
#pragma unroll
    for (int o = 64; o > 0; o >>= 1) {
        if (li < o) sred[t] += sred[t + o];
        __syncthreads();
    }
    if (li == 0) {
        ssum[h] = sred[t];
        g_cm  [(b * 4 + h) * NCHUNK + chunk] = sm[h];
        g_csum[(b * 4 + h) * NCHUNK + chunk] = sred[t];
    }
    __syncthreads();

    // partial weighted enc sum: thread (h, e = li)
    int nl = max(0, min(CLEN, len - l0));
    const float* encb = g_enc + ((size_t)b * LSTRIDE + l0) * HID + li;
    const float* wh = ssc + h * CLEN;
    float a0 = 0.f, a1 = 0.f, a2 = 0.f, a3 = 0.f;
    int l = 0;
    for (; l + 3 < nl; l += 4) {
        a0 = fmaf(wh[l],     __ldg(&encb[(size_t)l * HID]),       a0);
        a1 = fmaf(wh[l + 1], __ldg(&encb[(size_t)(l + 1) * HID]), a1);
        a2 = fmaf(wh[l + 2], __ldg(&encb[(size_t)(l + 2) * HID]), a2);
        a3 = fmaf(wh[l + 3], __ldg(&encb[(size_t)(l + 3) * HID]), a3);
    }
    for (; l < nl; l++) a0 = fmaf(wh[l], __ldg(&encb[(size_t)l * HID]), a0);
    g_part[((size_t)b * NCHUNK + chunk) * 512 + t] = (a0 + a1) + (a2 + a3);
}

// ---------------------------------------------------------------------------
// Kernel 5: rescale-combine. grid B, 512 threads, thread = (h = t>>7, e).
// ---------------------------------------------------------------------------
__global__ __launch_bounds__(512) void k_attnB(float* __restrict__ out)
{
    int b = blockIdx.x;
    int t = threadIdx.x;
    int h = t >> 7;
    int bh = b * 4 + h;

    float m = -1e30f;
#pragma unroll
    for (int c = 0; c < NCHUNK; c++) m = fmaxf(m, g_cm[bh * NCHUNK + c]);

    float denom = 0.f, num = 0.f;
#pragma unroll
    for (int c = 0; c < NCHUNK; c++) {
        float f = expf(g_cm[bh * NCHUNK + c] - m);
        denom = fmaf(g_csum[bh * NCHUNK + c], f, denom);
        num   = fmaf(g_part[((size_t)b * NCHUNK + c) * 512 + t], f, num);
    }
    out[b * 512 + t] = num / denom;
}

// ---------------------------------------------------------------------------
extern "C" void kernel_launch(void* const* d_in, const int* in_sizes, int n_in,
                              void* d_out, int out_size)
{
    const float* times    = (const float*)d_in[0];
    const int*   time_ptr = (const int*)  d_in[1];
    const float* X        = (const float*)d_in[2];
    const int*   M        = (const int*)  d_in[3];
    const float* W0 = (const float*)d_in[6];
    const float* b0 = (const float*)d_in[7];
    const float* W1 = (const float*)d_in[8];
    const float* b1 = (const float*)d_in[9];
    const float* W2 = (const float*)d_in[10];
    const float* b2 = (const float*)d_in[11];
    const float* Wq = (const float*)d_in[12];
    const float* bq = (const float*)d_in[13];
    const float* Wk = (const float*)d_in[14];
    const float* bk = (const float*)d_in[15];

    int R       = in_sizes[0];
    int n_times = in_sizes[0];
    int V       = in_sizes[2] / R;
    int B       = in_sizes[5];

    k_rows<<<(R * 32 + 255) / 256, 256>>>(times, time_ptr, M, R, V, n_times);
    k_compact<<<B, 256>>>(X, R, V, B);
    k_mlp<<<B * 64 + 1, 128>>>(W0, b0, W1, b1, W2, b2, Wk, bk, Wq, bq, B);
    dim3 gs(B, NCHUNK);
    k_attnA<<<gs, 512>>>();
    k_attnB<<<B, 512>>>((float*)d_out);
}

// round 11
// speedup vs baseline: 1.2199x; 1.2199x over previous
#include <cuda_runtime.h>
#include <math.h>

// ---------------------------------------------------------------------------
// SeFT network, round 10:
//  - gather: single fused kernel (ballot + prefix + scatter per patient)
//  - k_mlp: R8-validated dense128 inner loop (2 rows x 16 obs / thread),
//    but 64-obs tiles (256 threads, dynamic smem) -> half the weight L2
//    traffic of the 32-obs version
//  - attention: R8 flash two-pass, NCHUNK=8, warp-shuffle reductions,
//    8-way unrolled enc-sum
// ---------------------------------------------------------------------------

#define BMAX    32
#define LSTRIDE 2048
#define NCHUNK  8           // LSTRIDE / 256
#define HID     128
#define NIN     34
#define TOBS    64          // obs per MLP tile
#define NTILE   32          // LSTRIDE / TOBS
#define ASTR    68          // activation row stride (floats): 64 + 4 pad

typedef unsigned long long ull;

__device__ float    g_St[BMAX * LSTRIDE];
__device__ float    g_Sc[BMAX * LSTRIDE];
__device__ float    g_Sx[BMAX * LSTRIDE];
__device__ int      g_lens[BMAX];
__device__ int      g_maxlen;
__device__ float    g_enc[(size_t)BMAX * LSTRIDE * HID];   // [b][l][e]
__device__ float    g_kT [(size_t)BMAX * HID * LSTRIDE];   // [b][e][l]
__device__ float    g_q  [BMAX * HID];
__device__ float    g_cm  [BMAX * 4 * NCHUNK];             // chunk max
__device__ float    g_csum[BMAX * 4 * NCHUNK];             // chunk expsum
__device__ float    g_part[(size_t)BMAX * NCHUNK * 512];   // [b][chunk][h*128+e]

// ---- packed fp32x2 helpers -------------------------------------------------
__device__ __forceinline__ ull pack2(float x, float y) {
    ull r;
    asm("mov.b64 %0, {%1, %2};" : "=l"(r) : "f"(x), "f"(y));
    return r;
}
__device__ __forceinline__ void unpack2(ull v, float& lo, float& hi) {
    asm("mov.b64 {%0, %1}, %2;" : "=f"(lo), "=f"(hi) : "l"(v));
}
__device__ __forceinline__ ull ffma2(ull a, ull b, ull c) {
    ull d;
    asm("fma.rn.f32x2 %0, %1, %2, %3;" : "=l"(d) : "l"(a), "l"(b), "l"(c));
    return d;
}

// ---------------------------------------------------------------------------
// Kernel 1: fused gather. One block per patient (256 threads, 8 warps):
// ballot per row (coalesced M reads), time via binary search, smem prefix
// sum, warp-per-row scatter of (t, col, val).
// ---------------------------------------------------------------------------
__global__ __launch_bounds__(256) void k_compact(
    const float* __restrict__ times,
    const int*   __restrict__ time_ptr,
    const float* __restrict__ X,
    const int*   __restrict__ M,
    int R, int V, int B, int n_times)
{
    int b = blockIdx.x;
    int t = threadIdx.x;
    int rpp = R / B;
    int r0 = b * rpp;
    int lane = t & 31, w = t >> 5;

    __shared__ int      scnt[256];
    __shared__ int      sinc[256];
    __shared__ unsigned smask[256];
    __shared__ float    stime[256];

    scnt[t] = 0;           // rows >= rpp contribute 0 (no race: disjoint idx)

    for (int lr = w; lr < rpp; lr += 8) {
        int r = r0 + lr;
        int m = (lane < V) ? (M[r * V + lane] != 0) : 0;
        unsigned mask = __ballot_sync(0xffffffffu, m);
        if (lane == 0) {
            smask[lr] = mask;
            scnt[lr]  = __popc(mask);
            int lo = 0, hi = n_times - 1;
            while (lo < hi) {
                int mid = (lo + hi + 1) >> 1;
                if (time_ptr[mid] <= r) lo = mid; else hi = mid - 1;
            }
            stime[lr] = times[lo];
        }
    }
    __syncthreads();

    int cnt = scnt[t];
    sinc[t] = cnt;
    __syncthreads();
    for (int off = 1; off < 256; off <<= 1) {
        int v = (t >= off) ? sinc[t - off] : 0;
        __syncthreads();
        sinc[t] += v;
        __syncthreads();
    }
    int tot = sinc[255];

    for (int lr = w; lr < rpp; lr += 8) {
        int r = r0 + lr;
        unsigned mask = smask[lr];
        float tv = stime[lr];
        int start = sinc[lr] - scnt[lr];
        if (lane < V && ((mask >> lane) & 1u)) {
            int pos = start + __popc(mask & ((1u << lane) - 1u));
            if (pos < LSTRIDE) {
                g_St[b * LSTRIDE + pos] = tv;
                g_Sc[b * LSTRIDE + pos] = (float)lane;
                g_Sx[b * LSTRIDE + pos] = X[r * V + lane];
            }
        }
    }
    if (t == 0) {
        int L = min(tot, LSTRIDE);
        g_lens[b] = L;
        atomicMax(&g_maxlen, L);   // idempotent across replays
    }
}

// ---------------------------------------------------------------------------
// 128->128 dense layer, f32x2, weights staged in smem chunks of 32 k-rows.
// (R8-validated inner loop.) Thread (r = tid&63, h = tid>>6) computes output
// rows r, r+64 for obs [h*16, h*16+16). wbuf[kk*129 + o] conflict-free.
// 256 threads per block.
// ---------------------------------------------------------------------------
__device__ __forceinline__ void dense128(const float* __restrict__ W,
                                         const float* __restrict__ bias,
                                         const float* sIn, float* wbuf,
                                         ull accA[8], ull accB[8],
                                         int r, int h, int tid)
{
    float bA = __ldg(&bias[r]);
    float bB = __ldg(&bias[r + 64]);
    ull iA = pack2(bA, bA), iB = pack2(bB, bB);
#pragma unroll
    for (int j = 0; j < 8; j++) { accA[j] = iA; accB[j] = iB; }

    for (int c = 0; c < 4; c++) {
        // stage 128x32 chunk, coalesced LDG.128, conflict-free STS
        for (int i4 = tid; i4 < 1024; i4 += 256) {
            int e  = i4 << 2;        // element = o*32 + kk
            int o  = e >> 5;
            int kk = e & 31;
            float4 v = __ldg((const float4*)(W + o * HID + c * 32 + kk));
            wbuf[kk * 129 + o]       = v.x;
            wbuf[(kk + 1) * 129 + o] = v.y;
            wbuf[(kk + 2) * 129 + o] = v.z;
            wbuf[(kk + 3) * 129 + o] = v.w;
        }
        __syncthreads();
#pragma unroll 4
        for (int kk = 0; kk < 32; kk++) {
            float wA = wbuf[kk * 129 + r];
            float wB = wbuf[kk * 129 + 64 + r];
            ull wA2 = pack2(wA, wA), wB2 = pack2(wB, wB);
            const ulonglong2* row =
                (const ulonglong2*)(sIn + (c * 32 + kk) * ASTR + h * 16);
#pragma unroll
            for (int p = 0; p < 4; p++) {
                ulonglong2 v = row[p];
                accA[2 * p]     = ffma2(v.x, wA2, accA[2 * p]);
                accA[2 * p + 1] = ffma2(v.y, wA2, accA[2 * p + 1]);
                accB[2 * p]     = ffma2(v.x, wB2, accB[2 * p]);
                accB[2 * p + 1] = ffma2(v.y, wB2, accB[2 * p + 1]);
            }
        }
        __syncthreads();
    }
}

// relu epilogue into [k][obs] smem for rows r, r+64, obs group h
__device__ __forceinline__ void epi_relu(float* dst, ull accA[8], ull accB[8],
                                         int r, int h)
{
    float* dA = dst + r * ASTR + h * 16;
    float* dB = dst + (r + 64) * ASTR + h * 16;
#pragma unroll
    for (int j = 0; j < 8; j++) {
        float lo, hi;
        unpack2(accA[j], lo, hi);
        *(ull*)(dA + 2 * j) = pack2(fmaxf(lo, 0.f), fmaxf(hi, 0.f));
        unpack2(accB[j], lo, hi);
        *(ull*)(dB + 2 * j) = pack2(fmaxf(lo, 0.f), fmaxf(hi, 0.f));
    }
}

// ---------------------------------------------------------------------------
// Kernel 2: fused MLP + projection, 64-obs tiles, 256 threads, dynamic smem.
// Block 0 = query path (lastfeat inline, Wq -> g_q). Others: enc + kT.
//   L0: in sf, w sA, out sA      L1: in sA, w sB, out sB
//   L2: in sB, w sA, out sA+enc  Pr: in sA, w sB, out global
// ---------------------------------------------------------------------------
__global__ __launch_bounds__(256) void k_mlp(
    const float* __restrict__ W0, const float* __restrict__ b0,
    const float* __restrict__ W1, const float* __restrict__ b1,
    const float* __restrict__ W2, const float* __restrict__ b2,
    const float* __restrict__ Wk, const float* __restrict__ bk,
    const float* __restrict__ Wq, const float* __restrict__ bq,
    int B)
{
    extern __shared__ __align__(16) float smem[];
    float* sf = smem;                      // NIN * ASTR
    float* sA = smem + NIN * ASTR;         // HID * ASTR
    float* sB = sA + HID * ASTR;           // HID * ASTR

    int tid = threadIdx.x;
    int r = tid & 63;
    int h = tid >> 6;

    bool special = (blockIdx.x == 0);
    int b = 0, l0 = 0, nv = 0;
    if (!special) {
        int bi = blockIdx.x - 1;
        b = bi >> 5;
        int lt = bi & (NTILE - 1);
        int len = g_lens[b];
        l0 = lt * TOBS;
        if (l0 >= len) return;
        nv = min(TOBS, len - l0);
    } else {
        nv = min(B, TOBS);
    }

    // stage W0 [128][34] into sA at stride 129 (dead until L0 epilogue)
    for (int i = tid; i < HID * NIN; i += 256) {
        int o = i / NIN, k = i - o * NIN;
        sA[k * 129 + o] = __ldg(&W0[i]);
    }

    // features into [k][obs] layout
    if (tid < TOBS) {
        int o = tid;
        float tv = 0.f, cv = 0.f, xv = 0.f;
        if (special) {
            int L = g_maxlen;
            if (o < nv && L >= 1 && g_lens[o] == L) {
                tv = g_St[o * LSTRIDE + L - 1];
                cv = g_Sc[o * LSTRIDE + L - 1];
                xv = g_Sx[o * LSTRIDE + L - 1];
            }
        } else if (o < nv) {
            tv = g_St[b * LSTRIDE + l0 + o];
            cv = g_Sc[b * LSTRIDE + l0 + o];
            xv = g_Sx[b * LSTRIDE + l0 + o];
        }
#pragma unroll
        for (int i = 0; i < 16; i++) {
            float ts = powf(100.0f, (float)i * (1.0f / 15.0f));
            float sn, cs;
            sincosf(tv / ts, &sn, &cs);
            sf[i * ASTR + o]        = sn;
            sf[(16 + i) * ASTR + o] = cs;
        }
        sf[32 * ASTR + o] = cv;
        sf[33 * ASTR + o] = xv;
    }
    __syncthreads();

    ull accA[8], accB[8];

    // ---- layer 0: 34 -> 128, relu (weights in sA, input sf) ----
    {
        float bA = __ldg(&b0[r]);
        float bB = __ldg(&b0[r + 64]);
        ull iA = pack2(bA, bA), iB = pack2(bB, bB);
#pragma unroll
        for (int j = 0; j < 8; j++) { accA[j] = iA; accB[j] = iB; }
#pragma unroll 2
        for (int k = 0; k < NIN; k++) {
            float wA = sA[k * 129 + r];
            float wB = sA[k * 129 + 64 + r];
            ull wA2 = pack2(wA, wA), wB2 = pack2(wB, wB);
            const ulonglong2* row = (const ulonglong2*)(sf + k * ASTR + h * 16);
#pragma unroll
            for (int p = 0; p < 4; p++) {
                ulonglong2 v = row[p];
                accA[2 * p]     = ffma2(v.x, wA2, accA[2 * p]);
                accA[2 * p + 1] = ffma2(v.y, wA2, accA[2 * p + 1]);
                accB[2 * p]     = ffma2(v.x, wB2, accB[2 * p]);
                accB[2 * p + 1] = ffma2(v.y, wB2, accB[2 * p + 1]);
            }
        }
        __syncthreads();            // weights in sA dead after this
        epi_relu(sA, accA, accB, r, h);
    }
    __syncthreads();

    // ---- layer 1: 128 -> 128, relu (in sA, weights+out sB) ----
    dense128(W1, b1, sA, sB, accA, accB, r, h, tid);
    epi_relu(sB, accA, accB, r, h);
    __syncthreads();

    // ---- layer 2 (enc): 128 -> 128, linear (in sB, weights+out sA) ----
    dense128(W2, b2, sB, sA, accA, accB, r, h, tid);
    {
        float vA[16], vB[16];
#pragma unroll
        for (int j = 0; j < 8; j++) {
            unpack2(accA[j], vA[2 * j], vA[2 * j + 1]);
            unpack2(accB[j], vB[2 * j], vB[2 * j + 1]);
        }
        float* dA = sA + r * ASTR + h * 16;
        float* dB = sA + (r + 64) * ASTR + h * 16;
#pragma unroll
        for (int j = 0; j < 8; j++) {
            *(ull*)(dA + 2 * j) = accA[j];
            *(ull*)(dB + 2 * j) = accB[j];
        }
        if (!special) {
#pragma unroll
            for (int o = 0; o < 16; o++) {
                int og = h * 16 + o;
                if (og < nv) {
                    size_t base = ((size_t)b * LSTRIDE + l0 + og) * HID;
                    g_enc[base + r]      = vA[o];
                    g_enc[base + 64 + r] = vB[o];
                }
            }
        }
    }
    __syncthreads();

    // ---- projection: Wk (normal) or Wq (special); in sA, weights sB ----
    dense128(special ? Wq : Wk, special ? bq : bk, sA, sB, accA, accB, r, h, tid);
    {
        float vA[16], vB[16];
#pragma unroll
        for (int j = 0; j < 8; j++) {
            unpack2(accA[j], vA[2 * j], vA[2 * j + 1]);
            unpack2(accB[j], vB[2 * j], vB[2 * j + 1]);
        }
        if (special) {
#pragma unroll
            for (int o = 0; o < 16; o++) {
                int og = h * 16 + o;
                if (og < nv) {
                    g_q[og * HID + r]      = vA[o];
                    g_q[og * HID + 64 + r] = vB[o];
                }
            }
        } else {
            float* gkA = g_kT + ((size_t)b * HID + r) * LSTRIDE + l0 + h * 16;
            float* gkB = g_kT + ((size_t)b * HID + 64 + r) * LSTRIDE + l0 + h * 16;
#pragma unroll
            for (int o = 0; o < 16; o += 4) {
                int og = h * 16 + o;
                if (og + 4 <= nv) {
                    *(float4*)(gkA + o) = make_float4(vA[o], vA[o+1], vA[o+2], vA[o+3]);
                    *(float4*)(gkB + o) = make_float4(vB[o], vB[o+1], vB[o+2], vB[o+3]);
                } else {
                    for (int m = 0; m < 4; m++)
                        if (og + m < nv) { gkA[o + m] = vA[o + m]; gkB[o + m] = vB[o + m]; }
                }
            }
        }
    }
}

// ---------------------------------------------------------------------------
// Kernel 3: flash attention pass A. grid (B, NCHUNK), 512 threads.
// Scores (2 heads/thread, coalesced over l), warp-shuffle reductions,
// 8-way unrolled partial weighted enc sum.
// ---------------------------------------------------------------------------
__global__ __launch_bounds__(512) void k_attnA()
{
    int b     = blockIdx.x;
    int chunk = blockIdx.y;
    int t     = threadIdx.x;
    int len   = min(g_lens[b], LSTRIDE);
    int l0    = chunk * 256;

    __shared__ float sq[HID];
    __shared__ float ssc[4 * 256];
    __shared__ float sredw[16];
    __shared__ float sm[4];

    if (t < HID) sq[t] = g_q[b * HID + t];
    __syncthreads();

    const float scale = 0.17677669529663687f; // 1/sqrt(32)

    // scores: thread (li = t&255, head pair hp = (t>>8)*2)
    {
        int li = t & 255;
        int hp = (t >> 8) << 1;
        int l  = l0 + li;
        float s0 = -1e30f, s1 = -1e30f;
        if (l < len) {
            const float* kb = g_kT + (size_t)b * HID * LSTRIDE + l;
            float a0 = 0.f, a1 = 0.f, c0 = 0.f, c1 = 0.f;
#pragma unroll 8
            for (int e2 = 0; e2 < 32; e2 += 2) {
                a0 = fmaf(__ldg(&kb[(size_t)(hp * 32 + e2) * LSTRIDE]),
                          sq[hp * 32 + e2], a0);
                c0 = fmaf(__ldg(&kb[(size_t)(hp * 32 + e2 + 1) * LSTRIDE]),
                          sq[hp * 32 + e2 + 1], c0);
                a1 = fmaf(__ldg(&kb[(size_t)((hp + 1) * 32 + e2) * LSTRIDE]),
                          sq[(hp + 1) * 32 + e2], a1);
                c1 = fmaf(__ldg(&kb[(size_t)((hp + 1) * 32 + e2 + 1) * LSTRIDE]),
                          sq[(hp + 1) * 32 + e2 + 1], c1);
            }
            s0 = (a0 + c0) * scale;
            s1 = (a1 + c1) * scale;
        }
        ssc[hp * 256 + li]       = s0;
        ssc[(hp + 1) * 256 + li] = s1;
    }
    __syncthreads();

    int h = t >> 7, i = t & 127;
    int wid = t >> 5, lane = t & 31;

    // chunk max per head: warp shuffle + 1 combine
    {
        float v = fmaxf(ssc[h * 256 + i], ssc[h * 256 + 128 + i]);
#pragma unroll
        for (int o = 16; o > 0; o >>= 1)
            v = fmaxf(v, __shfl_xor_sync(0xffffffffu, v, o));
        if (lane == 0) sredw[wid] = v;
    }
    __syncthreads();
    if (t < 4) {
        sm[t] = fmaxf(fmaxf(sredw[t * 4], sredw[t * 4 + 1]),
                      fmaxf(sredw[t * 4 + 2], sredw[t * 4 + 3]));
    }
    __syncthreads();

    // exp weights (zero for padded l): each thread 2 elements
#pragma unroll
    for (int j = 0; j < 2; j++) {
        int idx = t + j * 512;
        int hh = idx >> 8, li2 = idx & 255;
        float wv = (l0 + li2 < len) ? expf(ssc[idx] - sm[hh]) : 0.f;
        ssc[idx] = wv;
    }
    __syncthreads();

    // chunk expsum per head
    {
        float v = ssc[h * 256 + i] + ssc[h * 256 + 128 + i];
#pragma unroll
        for (int o = 16; o > 0; o >>= 1)
            v += __shfl_xor_sync(0xffffffffu, v, o);
        if (lane == 0) sredw[wid] = v;
    }
    __syncthreads();
    if (t < 4) {
        float s = (sredw[t * 4] + sredw[t * 4 + 1]) + (sredw[t * 4 + 2] + sredw[t * 4 + 3]);
        g_cm  [(b * 4 + t) * NCHUNK + chunk] = sm[t];
        g_csum[(b * 4 + t) * NCHUNK + chunk] = s;
    }

    // partial weighted enc sum: thread (h, e = i), 8-way unrolled
    int nl = max(0, min(256, len - l0));
    const float* encb = g_enc + ((size_t)b * LSTRIDE + l0) * HID + i;
    const float* wh = ssc + h * 256;
    float a0 = 0.f, a1 = 0.f, a2 = 0.f, a3 = 0.f;
    float a4 = 0.f, a5 = 0.f, a6 = 0.f, a7 = 0.f;
    int l = 0;
    for (; l + 7 < nl; l += 8) {
        a0 = fmaf(wh[l],     __ldg(&encb[(size_t)l * HID]),       a0);
        a1 = fmaf(wh[l + 1], __ldg(&encb[(size_t)(l + 1) * HID]), a1);
        a2 = fmaf(wh[l + 2], __ldg(&encb[(size_t)(l + 2) * HID]), a2);
        a3 = fmaf(wh[l + 3], __ldg(&encb[(size_t)(l + 3) * HID]), a3);
        a4 = fmaf(wh[l + 4], __ldg(&encb[(size_t)(l + 4) * HID]), a4);
        a5 = fmaf(wh[l + 5], __ldg(&encb[(size_t)(l + 5) * HID]), a5);
        a6 = fmaf(wh[l + 6], __ldg(&encb[(size_t)(l + 6) * HID]), a6);
        a7 = fmaf(wh[l + 7], __ldg(&encb[(size_t)(l + 7) * HID]), a7);
    }
    for (; l < nl; l++) a0 = fmaf(wh[l], __ldg(&encb[(size_t)l * HID]), a0);
    g_part[((size_t)b * NCHUNK + chunk) * 512 + t] =
        ((a0 + a1) + (a2 + a3)) + ((a4 + a5) + (a6 + a7));
}

// ---------------------------------------------------------------------------
// Kernel 4: rescale-combine. grid B, 512 threads, thread = (h = t>>7, e).
// ---------------------------------------------------------------------------
__global__ __launch_bounds__(512) void k_attnB(float* __restrict__ out)
{
    int b = blockIdx.x;
    int t = threadIdx.x;
    int h = t >> 7;
    int bh = b * 4 + h;

    float m = -1e30f;
#pragma unroll
    for (int c = 0; c < NCHUNK; c++) m = fmaxf(m, g_cm[bh * NCHUNK + c]);

    float denom = 0.f, num = 0.f;
#pragma unroll
    for (int c = 0; c < NCHUNK; c++) {
        float f = expf(g_cm[bh * NCHUNK + c] - m);
        denom = fmaf(g_csum[bh * NCHUNK + c], f, denom);
        num   = fmaf(g_part[((size_t)b * NCHUNK + c) * 512 + t], f, num);
    }
    out[b * 512 + t] = num / denom;
}

// ---------------------------------------------------------------------------
extern "C" void kernel_launch(void* const* d_in, const int* in_sizes, int n_in,
                              void* d_out, int out_size)
{
    const float* times    = (const float*)d_in[0];
    const int*   time_ptr = (const int*)  d_in[1];
    const float* X        = (const float*)d_in[2];
    const int*   M        = (const int*)  d_in[3];
    const float* W0 = (const float*)d_in[6];
    const float* b0 = (const float*)d_in[7];
    const float* W1 = (const float*)d_in[8];
    const float* b1 = (const float*)d_in[9];
    const float* W2 = (const float*)d_in[10];
    const float* b2 = (const float*)d_in[11];
    const float* Wq = (const float*)d_in[12];
    const float* bq = (const float*)d_in[13];
    const float* Wk = (const float*)d_in[14];
    const float* bk = (const float*)d_in[15];

    int R       = in_sizes[0];
    int n_times = in_sizes[0];
    int V       = in_sizes[2] / R;
    int B       = in_sizes[5];

    const int MLP_SMEM = (NIN + 2 * HID) * ASTR * (int)sizeof(float); // 78880B
    cudaFuncSetAttribute(k_mlp, cudaFuncAttributeMaxDynamicSharedMemorySize,
                         MLP_SMEM);

    k_compact<<<B, 256>>>(times, time_ptr, X, M, R, V, B, n_times);
    k_mlp<<<B * NTILE + 1, 256, MLP_SMEM>>>(W0, b0, W1, b1, W2, b2,
                                            Wk, bk, Wq, bq, B);
    dim3 gs(B, NCHUNK);
    k_attnA<<<gs, 512>>>();
    k_attnB<<<B, 512>>>((float*)d_out);
}

// round 12
// speedup vs baseline: 1.5093x; 1.2373x over previous
#include <cuda_runtime.h>
#include <math.h>

// ---------------------------------------------------------------------------
// SeFT network, round 11:
//  - gather: fused ballot compaction (validated R10)
//  - k_mlp: R8-validated version verbatim (128 thr, 32-obs tiles, static smem)
//  - attention pass A: smem-staged K and ENC tiles per 128-l chunk
//    (coalesced DRAM, conflict-free smem), shuffle softmax, 4-head-per-LDS
//    weighted sum; pass B rescale-combine (NCHUNK=16)
// ---------------------------------------------------------------------------

#define BMAX    32
#define LSTRIDE 2048
#define NCHUNK  16          // LSTRIDE / CLEN
#define CLEN    128         // l per attention chunk
#define HID     128
#define NIN     34
#define ASTR    36          // MLP activation row stride (floats)

typedef unsigned long long ull;

__device__ float    g_St[BMAX * LSTRIDE];
__device__ float    g_Sc[BMAX * LSTRIDE];
__device__ float    g_Sx[BMAX * LSTRIDE];
__device__ int      g_lens[BMAX];
__device__ int      g_maxlen;
__device__ float    g_enc[(size_t)BMAX * LSTRIDE * HID];   // [b][l][e]
__device__ float    g_kT [(size_t)BMAX * HID * LSTRIDE];   // [b][e][l]
__device__ float    g_q  [BMAX * HID];
__device__ float    g_cm  [BMAX * 4 * NCHUNK];             // chunk max
__device__ float    g_csum[BMAX * 4 * NCHUNK];             // chunk expsum
__device__ float    g_part[(size_t)BMAX * NCHUNK * 512];   // [b][chunk][h*128+e]

// ---- packed fp32x2 helpers -------------------------------------------------
__device__ __forceinline__ ull pack2(float x, float y) {
    ull r;
    asm("mov.b64 %0, {%1, %2};" : "=l"(r) : "f"(x), "f"(y));
    return r;
}
__device__ __forceinline__ void unpack2(ull v, float& lo, float& hi) {
    asm("mov.b64 {%0, %1}, %2;" : "=f"(lo), "=f"(hi) : "l"(v));
}
__device__ __forceinline__ ull ffma2(ull a, ull b, ull c) {
    ull d;
    asm("fma.rn.f32x2 %0, %1, %2, %3;" : "=l"(d) : "l"(a), "l"(b), "l"(c));
    return d;
}

// ---------------------------------------------------------------------------
// Kernel 1: fused gather. One block per patient (256 threads, 8 warps).
// ---------------------------------------------------------------------------
__global__ __launch_bounds__(256) void k_compact(
    const float* __restrict__ times,
    const int*   __restrict__ time_ptr,
    const float* __restrict__ X,
    const int*   __restrict__ M,
    int R, int V, int B, int n_times)
{
    int b = blockIdx.x;
    int t = threadIdx.x;
    int rpp = R / B;
    int r0 = b * rpp;
    int lane = t & 31, w = t >> 5;

    __shared__ int      scnt[256];
    __shared__ int      sinc[256];
    __shared__ unsigned smask[256];
    __shared__ float    stime[256];

    scnt[t] = 0;

    for (int lr = w; lr < rpp; lr += 8) {
        int r = r0 + lr;
        int m = (lane < V) ? (M[r * V + lane] != 0) : 0;
        unsigned mask = __ballot_sync(0xffffffffu, m);
        if (lane == 0) {
            smask[lr] = mask;
            scnt[lr]  = __popc(mask);
            int lo = 0, hi = n_times - 1;
            while (lo < hi) {
                int mid = (lo + hi + 1) >> 1;
                if (time_ptr[mid] <= r) lo = mid; else hi = mid - 1;
            }
            stime[lr] = times[lo];
        }
    }
    __syncthreads();

    int cnt = scnt[t];
    sinc[t] = cnt;
    __syncthreads();
    for (int off = 1; off < 256; off <<= 1) {
        int v = (t >= off) ? sinc[t - off] : 0;
        __syncthreads();
        sinc[t] += v;
        __syncthreads();
    }
    int tot = sinc[255];

    for (int lr = w; lr < rpp; lr += 8) {
        int r = r0 + lr;
        unsigned mask = smask[lr];
        float tv = stime[lr];
        int start = sinc[lr] - scnt[lr];
        if (lane < V && ((mask >> lane) & 1u)) {
            int pos = start + __popc(mask & ((1u << lane) - 1u));
            if (pos < LSTRIDE) {
                g_St[b * LSTRIDE + pos] = tv;
                g_Sc[b * LSTRIDE + pos] = (float)lane;
                g_Sx[b * LSTRIDE + pos] = X[r * V + lane];
            }
        }
    }
    if (t == 0) {
        int L = min(tot, LSTRIDE);
        g_lens[b] = L;
        atomicMax(&g_maxlen, L);   // idempotent across replays
    }
}

// ---------------------------------------------------------------------------
// 128->128 dense layer, f32x2, weights staged in smem chunks of 32 k-rows.
// (R8-validated.) Thread (r = tid&63, h = tid>>6) computes output rows
// r, r+64 for obs [h*16, h*16+16). wbuf[kk*129 + o] conflict-free.
// ---------------------------------------------------------------------------
__device__ __forceinline__ void dense128(const float* __restrict__ W,
                                         const float* __restrict__ bias,
                                         const float* sIn, float* wbuf,
                                         ull accA[8], ull accB[8],
                                         int r, int h, int tid)
{
    float bA = __ldg(&bias[r]);
    float bB = __ldg(&bias[r + 64]);
    ull iA = pack2(bA, bA), iB = pack2(bB, bB);
#pragma unroll
    for (int j = 0; j < 8; j++) { accA[j] = iA; accB[j] = iB; }

    for (int c = 0; c < 4; c++) {
        for (int i4 = tid; i4 < 1024; i4 += 128) {
            int e  = i4 << 2;
            int o  = e >> 5;
            int kk = e & 31;
            float4 v = __ldg((const float4*)(W + o * HID + c * 32 + kk));
            wbuf[kk * 129 + o]       = v.x;
            wbuf[(kk + 1) * 129 + o] = v.y;
            wbuf[(kk + 2) * 129 + o] = v.z;
            wbuf[(kk + 3) * 129 + o] = v.w;
        }
        __syncthreads();
#pragma unroll 4
        for (int kk = 0; kk < 32; kk++) {
            float wA = wbuf[kk * 129 + r];
            float wB = wbuf[kk * 129 + 64 + r];
            ull wA2 = pack2(wA, wA), wB2 = pack2(wB, wB);
            const ulonglong2* row =
                (const ulonglong2*)(sIn + (c * 32 + kk) * ASTR + h * 16);
#pragma unroll
            for (int p = 0; p < 4; p++) {
                ulonglong2 v = row[p];
                accA[2 * p]     = ffma2(v.x, wA2, accA[2 * p]);
                accA[2 * p + 1] = ffma2(v.y, wA2, accA[2 * p + 1]);
                accB[2 * p]     = ffma2(v.x, wB2, accB[2 * p]);
                accB[2 * p + 1] = ffma2(v.y, wB2, accB[2 * p + 1]);
            }
        }
        __syncthreads();
    }
}

__device__ __forceinline__ void epi_relu(float* dst, ull accA[8], ull accB[8],
                                         int r, int h)
{
    float* dA = dst + r * ASTR + h * 16;
    float* dB = dst + (r + 64) * ASTR + h * 16;
#pragma unroll
    for (int j = 0; j < 8; j++) {
        float lo, hi;
        unpack2(accA[j], lo, hi);
        *(ull*)(dA + 2 * j) = pack2(fmaxf(lo, 0.f), fmaxf(hi, 0.f));
        unpack2(accB[j], lo, hi);
        *(ull*)(dB + 2 * j) = pack2(fmaxf(lo, 0.f), fmaxf(hi, 0.f));
    }
}

// ---------------------------------------------------------------------------
// Kernel 2: fused MLP + projection, 32-obs tiles (R8-validated).
// Block 0 = query path (lastfeat inline, Wq -> g_q). Others: enc + kT.
// ---------------------------------------------------------------------------
__global__ __launch_bounds__(128) void k_mlp(
    const float* __restrict__ W0, const float* __restrict__ b0,
    const float* __restrict__ W1, const float* __restrict__ b1,
    const float* __restrict__ W2, const float* __restrict__ b2,
    const float* __restrict__ Wk, const float* __restrict__ bk,
    const float* __restrict__ Wq, const float* __restrict__ bq,
    int B)
{
    __shared__ __align__(16) float sf[NIN * ASTR];
    __shared__ __align__(16) float sA[HID * ASTR];
    __shared__ __align__(16) float sB[HID * ASTR];

    int tid = threadIdx.x;
    int r = tid & 63;
    int h = tid >> 6;

    bool special = (blockIdx.x == 0);
    int b = 0, l0 = 0, nv = 0;
    if (!special) {
        int bi = blockIdx.x - 1;
        b = bi >> 6;
        int lt = bi & 63;
        int len = g_lens[b];
        l0 = lt * 32;
        if (l0 >= len) return;
        nv = min(32, len - l0);
    } else {
        nv = min(B, 32);
    }

    for (int i = tid; i < HID * NIN; i += 128) {
        int o = i / NIN, k = i - o * NIN;
        sA[k * 129 + o] = __ldg(&W0[i]);
    }

    if (tid < 32) {
        int o = tid;
        float tv = 0.f, cv = 0.f, xv = 0.f;
        if (special) {
            int L = g_maxlen;
            if (o < nv && L >= 1 && g_lens[o] == L) {
                tv = g_St[o * LSTRIDE + L - 1];
                cv = g_Sc[o * LSTRIDE + L - 1];
                xv = g_Sx[o * LSTRIDE + L - 1];
            }
        } else if (o < nv) {
            tv = g_St[b * LSTRIDE + l0 + o];
            cv = g_Sc[b * LSTRIDE + l0 + o];
            xv = g_Sx[b * LSTRIDE + l0 + o];
        }
#pragma unroll
        for (int i = 0; i < 16; i++) {
            float ts = powf(100.0f, (float)i * (1.0f / 15.0f));
            float sn, cs;
            sincosf(tv / ts, &sn, &cs);
            sf[i * ASTR + o]        = sn;
            sf[(16 + i) * ASTR + o] = cs;
        }
        sf[32 * ASTR + o] = cv;
        sf[33 * ASTR + o] = xv;
    }
    __syncthreads();

    ull accA[8], accB[8];

    // ---- layer 0 ----
    {
        float bA = __ldg(&b0[r]);
        float bB = __ldg(&b0[r + 64]);
        ull iA = pack2(bA, bA), iB = pack2(bB, bB);
#pragma unroll
        for (int j = 0; j < 8; j++) { accA[j] = iA; accB[j] = iB; }
#pragma unroll 2
        for (int k = 0; k < NIN; k++) {
            float wA = sA[k * 129 + r];
            float wB = sA[k * 129 + 64 + r];
            ull wA2 = pack2(wA, wA), wB2 = pack2(wB, wB);
            const ulonglong2* row = (const ulonglong2*)(sf + k * ASTR + h * 16);
#pragma unroll
            for (int p = 0; p < 4; p++) {
                ulonglong2 v = row[p];
                accA[2 * p]     = ffma2(v.x, wA2, accA[2 * p]);
                accA[2 * p + 1] = ffma2(v.y, wA2, accA[2 * p + 1]);
                accB[2 * p]     = ffma2(v.x, wB2, accB[2 * p]);
                accB[2 * p + 1] = ffma2(v.y, wB2, accB[2 * p + 1]);
            }
        }
        __syncthreads();
        epi_relu(sA, accA, accB, r, h);
    }
    __syncthreads();

    // ---- layer 1 ----
    dense128(W1, b1, sA, sB, accA, accB, r, h, tid);
    epi_relu(sB, accA, accB, r, h);
    __syncthreads();

    // ---- layer 2 (enc) ----
    dense128(W2, b2, sB, sA, accA, accB, r, h, tid);
    {
        float vA[16], vB[16];
#pragma unroll
        for (int j = 0; j < 8; j++) {
            unpack2(accA[j], vA[2 * j], vA[2 * j + 1]);
            unpack2(accB[j], vB[2 * j], vB[2 * j + 1]);
        }
        float* dA = sA + r * ASTR + h * 16;
        float* dB = sA + (r + 64) * ASTR + h * 16;
#pragma unroll
        for (int j = 0; j < 8; j++) {
            *(ull*)(dA + 2 * j) = accA[j];
            *(ull*)(dB + 2 * j) = accB[j];
        }
        if (!special) {
#pragma unroll
            for (int o = 0; o < 16; o++) {
                int og = h * 16 + o;
                if (og < nv) {
                    size_t base = ((size_t)b * LSTRIDE + l0 + og) * HID;
                    g_enc[base + r]      = vA[o];
                    g_enc[base + 64 + r] = vB[o];
                }
            }
        }
    }
    __syncthreads();

    // ---- projection ----
    dense128(special ? Wq : Wk, special ? bq : bk, sA, sB, accA, accB, r, h, tid);
    {
        float vA[16], vB[16];
#pragma unroll
        for (int j = 0; j < 8; j++) {
            unpack2(accA[j], vA[2 * j], vA[2 * j + 1]);
            unpack2(accB[j], vB[2 * j], vB[2 * j + 1]);
        }
        if (special) {
#pragma unroll
            for (int o = 0; o < 16; o++) {
                int og = h * 16 + o;
                if (og < nv) {
                    g_q[og * HID + r]      = vA[o];
                    g_q[og * HID + 64 + r] = vB[o];
                }
            }
        } else {
            float* gkA = g_kT + ((size_t)b * HID + r) * LSTRIDE + l0 + h * 16;
            float* gkB = g_kT + ((size_t)b * HID + 64 + r) * LSTRIDE + l0 + h * 16;
#pragma unroll
            for (int o = 0; o < 16; o += 4) {
                int og = h * 16 + o;
                if (og + 4 <= nv) {
                    *(float4*)(gkA + o) = make_float4(vA[o], vA[o+1], vA[o+2], vA[o+3]);
                    *(float4*)(gkB + o) = make_float4(vB[o], vB[o+1], vB[o+2], vB[o+3]);
                } else {
                    for (int m = 0; m < 4; m++)
                        if (og + m < nv) { gkA[o + m] = vA[o + m]; gkB[o + m] = vB[o + m]; }
                }
            }
        }
    }
}

// ---------------------------------------------------------------------------
// Kernel 3: attention pass A with smem-staged tiles. grid (B, NCHUNK), 512 thr.
// Dyn smem: sq[128] | sbuf[128*129] | sw4[512] | sredw[16] | smx[4]
// ---------------------------------------------------------------------------
__global__ __launch_bounds__(512) void k_attnA()
{
    int b = blockIdx.x, chunk = blockIdx.y, t = threadIdx.x;
    int len = min(g_lens[b], LSTRIDE);
    int l0 = chunk * CLEN;
    float* part = g_part + ((size_t)b * NCHUNK + chunk) * 512;

    if (l0 >= len) {
        part[t] = 0.f;
        if (t < 4) {
            g_cm  [(b * 4 + t) * NCHUNK + chunk] = -1e30f;
            g_csum[(b * 4 + t) * NCHUNK + chunk] = 0.f;
        }
        return;
    }

    extern __shared__ __align__(16) float dyn[];
    float* sq    = dyn;             // 128
    float* sbuf  = dyn + 128;       // 128*129 = 16512
    float* sw4   = sbuf + 16512;    // 512  ([l][ha])
    float* sredw = sw4 + 512;       // 16
    float* smx   = sredw + 16;      // 4

    int nl = min(CLEN, len - l0);
    if (t < HID) sq[t] = g_q[b * HID + t];

    // ---- stage K transposed: sbuf[l*129 + e] = kT[b][e][l0+l] ----
    // Mapping keeps warp-LDG on 4 full 128B segments and STS conflict-free.
    const float* kbase = g_kT + (size_t)b * HID * LSTRIDE + l0;
    for (int i = t; i < 4096; i += 512) {
        int e  = (i >> 3) & 127;
        int f4 = (i & 7) + ((i >> 10) << 3);
        float4 v = *(const float4*)(kbase + (size_t)e * LSTRIDE + f4 * 4);
        sbuf[(f4 * 4 + 0) * 129 + e] = v.x;
        sbuf[(f4 * 4 + 1) * 129 + e] = v.y;
        sbuf[(f4 * 4 + 2) * 129 + e] = v.z;
        sbuf[(f4 * 4 + 3) * 129 + e] = v.w;
    }
    __syncthreads();

    const float scale = 0.17677669529663687f; // 1/sqrt(32)
    int l = t & 127, ha = t >> 7;
    int wid = t >> 5, lane = t & 31;

    // ---- scores from smem (lanes along l -> conflict-free) ----
    float s = -1e30f;
    if (l < nl) {
        const float* kr = sbuf + l * 129 + ha * 32;
        const float* qr = sq + ha * 32;
        float a0 = 0.f, a1 = 0.f, a2 = 0.f, a3 = 0.f;
#pragma unroll
        for (int j = 0; j < 32; j += 4) {
            a0 = fmaf(kr[j],     qr[j],     a0);
            a1 = fmaf(kr[j + 1], qr[j + 1], a1);
            a2 = fmaf(kr[j + 2], qr[j + 2], a2);
            a3 = fmaf(kr[j + 3], qr[j + 3], a3);
        }
        s = ((a0 + a1) + (a2 + a3)) * scale;
    }

    // ---- chunk max per head (4 warps per head) ----
    {
        float v = s;
#pragma unroll
        for (int o = 16; o > 0; o >>= 1)
            v = fmaxf(v, __shfl_xor_sync(0xffffffffu, v, o));
        if (lane == 0) sredw[wid] = v;
    }
    __syncthreads();
    if (t < 4)
        smx[t] = fmaxf(fmaxf(sredw[t * 4], sredw[t * 4 + 1]),
                       fmaxf(sredw[t * 4 + 2], sredw[t * 4 + 3]));
    __syncthreads();

    // ---- exp weights + chunk sum ----
    float wv = (l < nl) ? expf(s - smx[ha]) : 0.f;
    sw4[l * 4 + ha] = wv;
    {
        float v = wv;
#pragma unroll
        for (int o = 16; o > 0; o >>= 1)
            v += __shfl_xor_sync(0xffffffffu, v, o);
        if (lane == 0) sredw[wid] = v;
    }
    __syncthreads();
    if (t < 4) {
        g_cm  [(b * 4 + t) * NCHUNK + chunk] = smx[t];
        g_csum[(b * 4 + t) * NCHUNK + chunk] =
            (sredw[t * 4] + sredw[t * 4 + 1]) + (sredw[t * 4 + 2] + sredw[t * 4 + 3]);
    }
    __syncthreads();   // K reads done; sw4 visible

    // ---- stage ENC flat: sbuf[l*128 + e] (source layout matches -> memcpy) ----
    const float* ebase = g_enc + ((size_t)b * LSTRIDE + l0) * HID;
    for (int i = t; i < 4096; i += 512)
        *(float4*)(sbuf + i * 4) = *(const float4*)(ebase + i * 4);
    __syncthreads();

    // ---- weighted sum: thread (ls = t>>7, e = t&127); 4 heads per LDS ----
    int ls = t >> 7, e = t & 127;
    float ac0 = 0.f, ac1 = 0.f, ac2 = 0.f, ac3 = 0.f;
    int lstart = ls * 32;
#pragma unroll 8
    for (int li = 0; li < 32; li++) {
        int ll = lstart + li;
        float ev = sbuf[ll * 128 + e];
        float4 w4 = *(const float4*)(sw4 + ll * 4);
        ac0 = fmaf(ev, w4.x, ac0);
        ac1 = fmaf(ev, w4.y, ac1);
        ac2 = fmaf(ev, w4.z, ac2);
        ac3 = fmaf(ev, w4.w, ac3);
    }
    __syncthreads();   // all sbuf reads done
    *(float4*)(sbuf + ((ls * 128 + e) << 2)) = make_float4(ac0, ac1, ac2, ac3);
    __syncthreads();

    {
        int ha2 = t >> 7, e2 = t & 127;
        float rr = 0.f;
#pragma unroll
        for (int q = 0; q < 4; q++)
            rr += sbuf[((q * 128 + e2) << 2) + ha2];
        part[t] = rr;   // index = ha2*128 + e2 = t
    }
}

// ---------------------------------------------------------------------------
// Kernel 4: rescale-combine. grid B, 512 threads, thread = (h = t>>7, e).
// ---------------------------------------------------------------------------
__global__ __launch_bounds__(512) void k_attnB(float* __restrict__ out)
{
    int b = blockIdx.x;
    int t = threadIdx.x;
    int h = t >> 7;
    int bh = b * 4 + h;

    float m = -1e30f;
#pragma unroll
    for (int c = 0; c < NCHUNK; c++) m = fmaxf(m, g_cm[bh * NCHUNK + c]);

    float denom = 0.f, num = 0.f;
#pragma unroll
    for (int c = 0; c < NCHUNK; c++) {
        float f = expf(g_cm[bh * NCHUNK + c] - m);
        denom = fmaf(g_csum[bh * NCHUNK + c], f, denom);
        num   = fmaf(g_part[((size_t)b * NCHUNK + c) * 512 + t], f, num);
    }
    out[b * 512 + t] = num / denom;
}

// ---------------------------------------------------------------------------
extern "C" void kernel_launch(void* const* d_in, const int* in_sizes, int n_in,
                              void* d_out, int out_size)
{
    const float* times    = (const float*)d_in[0];
    const int*   time_ptr = (const int*)  d_in[1];
    const float* X        = (const float*)d_in[2];
    const int*   M        = (const int*)  d_in[3];
    const float* W0 = (const float*)d_in[6];
    const float* b0 = (const float*)d_in[7];
    const float* W1 = (const float*)d_in[8];
    const float* b1 = (const float*)d_in[9];
    const float* W2 = (const float*)d_in[10];
    const float* b2 = (const float*)d_in[11];
    const float* Wq = (const float*)d_in[12];
    const float* bq = (const float*)d_in[13];
    const float* Wk = (const float*)d_in[14];
    const float* bk = (const float*)d_in[15];

    int R       = in_sizes[0];
    int n_times = in_sizes[0];
    int V       = in_sizes[2] / R;
    int B       = in_sizes[5];

    const int ATTN_SMEM = (128 + 128 * 129 + 512 + 16 + 4) * (int)sizeof(float);
    cudaFuncSetAttribute(k_attnA, cudaFuncAttributeMaxDynamicSharedMemorySize,
                         ATTN_SMEM);

    k_compact<<<B, 256>>>(times, time_ptr, X, M, R, V, B, n_times);
    k_mlp<<<B * 64 + 1, 128>>>(W0, b0, W1, b1, W2, b2, Wk, bk, Wq, bq, B);
    dim3 gs(B, NCHUNK);
    k_attnA<<<gs, 512, ATTN_SMEM>>>();
    k_attnB<<<B, 512>>>((float*)d_out);
}

// round 16
// speedup vs baseline: 1.5102x; 1.0006x over previous
#include <cuda_runtime.h>
#include <math.h>

// ---------------------------------------------------------------------------
// SeFT network, round 15 (= R11 validated base + attnB regrid + fast scan):
//  - gather: fused ballot compaction, warp-shuffle prefix scan
//  - k_mlp: R8-validated dense128 (128 thr, 32-obs tiles, static smem)
//  - attention pass A: smem-staged K/ENC chunks (validated R11)
//  - attention pass B: grid (B*4) x 128
//  NOTE: tcgen05 unavailable — harness emits compute_103 PTX (no 'a' target),
//  ptxas rejects tcgen05.*. FP32 f32x2 path is the ceiling here.
// ---------------------------------------------------------------------------

#define BMAX    32
#define LSTRIDE 2048
#define NCHUNK  16          // LSTRIDE / CLEN
#define CLEN    128
#define HID     128
#define NIN     34
#define ASTR    36

typedef unsigned long long ull;

__device__ float    g_St[BMAX * LSTRIDE];
__device__ float    g_Sc[BMAX * LSTRIDE];
__device__ float    g_Sx[BMAX * LSTRIDE];
__device__ int      g_lens[BMAX];
__device__ int      g_maxlen;
__device__ float    g_enc[(size_t)BMAX * LSTRIDE * HID];   // [b][l][e]
__device__ float    g_kT [(size_t)BMAX * HID * LSTRIDE];   // [b][e][l]
__device__ float    g_q  [BMAX * HID];
__device__ float    g_cm  [BMAX * 4 * NCHUNK];
__device__ float    g_csum[BMAX * 4 * NCHUNK];
__device__ float    g_part[(size_t)BMAX * NCHUNK * 512];

// ---- packed fp32x2 helpers -------------------------------------------------
__device__ __forceinline__ ull pack2(float x, float y) {
    ull r;
    asm("mov.b64 %0, {%1, %2};" : "=l"(r) : "f"(x), "f"(y));
    return r;
}
__device__ __forceinline__ void unpack2(ull v, float& lo, float& hi) {
    asm("mov.b64 {%0, %1}, %2;" : "=f"(lo), "=f"(hi) : "l"(v));
}
__device__ __forceinline__ ull ffma2(ull a, ull b, ull c) {
    ull d;
    asm("fma.rn.f32x2 %0, %1, %2, %3;" : "=l"(d) : "l"(a), "l"(b), "l"(c));
    return d;
}

// ---------------------------------------------------------------------------
// Kernel 1: fused gather. One block per patient (256 threads, 8 warps).
// Prefix sum via warp-shuffle scan (2 barriers instead of 16).
// ---------------------------------------------------------------------------
__global__ __launch_bounds__(256) void k_compact(
    const float* __restrict__ times,
    const int*   __restrict__ time_ptr,
    const float* __restrict__ X,
    const int*   __restrict__ M,
    int R, int V, int B, int n_times)
{
    int b = blockIdx.x;
    int t = threadIdx.x;
    int rpp = R / B;
    int r0 = b * rpp;
    int lane = t & 31, w = t >> 5;

    __shared__ int      scnt[256];
    __shared__ int      sstart[256];
    __shared__ int      swsum[8];
    __shared__ unsigned smask[256];
    __shared__ float    stime[256];

    scnt[t] = 0;

    for (int lr = w; lr < rpp; lr += 8) {
        int r = r0 + lr;
        int m = (lane < V) ? (M[r * V + lane] != 0) : 0;
        unsigned mask = __ballot_sync(0xffffffffu, m);
        if (lane == 0) {
            smask[lr] = mask;
            scnt[lr]  = __popc(mask);
            int lo = 0, hi = n_times - 1;
            while (lo < hi) {
                int mid = (lo + hi + 1) >> 1;
                if (time_ptr[mid] <= r) lo = mid; else hi = mid - 1;
            }
            stime[lr] = times[lo];
        }
    }
    __syncthreads();

    // warp-shuffle inclusive scan of scnt
    int cnt = scnt[t];
    int v = cnt;
#pragma unroll
    for (int o = 1; o < 32; o <<= 1) {
        int u = __shfl_up_sync(0xffffffffu, v, o);
        if (lane >= o) v += u;
    }
    if (lane == 31) swsum[w] = v;
    __syncthreads();
    int woff = 0;
#pragma unroll
    for (int q = 0; q < 8; q++) woff += (q < w) ? swsum[q] : 0;
    int tot = 0;
#pragma unroll
    for (int q = 0; q < 8; q++) tot += swsum[q];
    sstart[t] = woff + v - cnt;
    __syncthreads();

    for (int lr = w; lr < rpp; lr += 8) {
        int r = r0 + lr;
        unsigned mask = smask[lr];
        float tv = stime[lr];
        int start = sstart[lr];
        if (lane < V && ((mask >> lane) & 1u)) {
            int pos = start + __popc(mask & ((1u << lane) - 1u));
            if (pos < LSTRIDE) {
                g_St[b * LSTRIDE + pos] = tv;
                g_Sc[b * LSTRIDE + pos] = (float)lane;
                g_Sx[b * LSTRIDE + pos] = X[r * V + lane];
            }
        }
    }
    if (t == 0) {
        int L = min(tot, LSTRIDE);
        g_lens[b] = L;
        atomicMax(&g_maxlen, L);   // idempotent across replays
    }
}

// ---------------------------------------------------------------------------
// 128->128 dense layer, f32x2, weights staged in smem chunks of 32 k-rows.
// (R8-validated, frozen.) Thread (r = tid&63, h = tid>>6) computes output
// rows r, r+64 for obs [h*16, h*16+16). wbuf[kk*129 + o] conflict-free.
// ---------------------------------------------------------------------------
__device__ __forceinline__ void dense128(const float* __restrict__ W,
                                         const float* __restrict__ bias,
                                         const float* sIn, float* wbuf,
                                         ull accA[8], ull accB[8],
                                         int r, int h, int tid)
{
    float bA = __ldg(&bias[r]);
    float bB = __ldg(&bias[r + 64]);
    ull iA = pack2(bA, bA), iB = pack2(bB, bB);
#pragma unroll
    for (int j = 0; j < 8; j++) { accA[j] = iA; accB[j] = iB; }

    for (int c = 0; c < 4; c++) {
        for (int i4 = tid; i4 < 1024; i4 += 128) {
            int e  = i4 << 2;
            int o  = e >> 5;
            int kk = e & 31;
            float4 v = __ldg((const float4*)(W + o * HID + c * 32 + kk));
            wbuf[kk * 129 + o]       = v.x;
            wbuf[(kk + 1) * 129 + o] = v.y;
            wbuf[(kk + 2) * 129 + o] = v.z;
            wbuf[(kk + 3) * 129 + o] = v.w;
        }
        __syncthreads();
#pragma unroll 4
        for (int kk = 0; kk < 32; kk++) {
            float wA = wbuf[kk * 129 + r];
            float wB = wbuf[kk * 129 + 64 + r];
            ull wA2 = pack2(wA, wA), wB2 = pack2(wB, wB);
            const ulonglong2* row =
                (const ulonglong2*)(sIn + (c * 32 + kk) * ASTR + h * 16);
#pragma unroll
            for (int p = 0; p < 4; p++) {
                ulonglong2 v = row[p];
                accA[2 * p]     = ffma2(v.x, wA2, accA[2 * p]);
                accA[2 * p + 1] = ffma2(v.y, wA2, accA[2 * p + 1]);
                accB[2 * p]     = ffma2(v.x, wB2, accB[2 * p]);
                accB[2 * p + 1] = ffma2(v.y, wB2, accB[2 * p + 1]);
            }
        }
        __syncthreads();
    }
}

__device__ __forceinline__ void epi_relu(float* dst, ull accA[8], ull accB[8],
                                         int r, int h)
{
    float* dA = dst + r * ASTR + h * 16;
    float* dB = dst + (r + 64) * ASTR + h * 16;
#pragma unroll
    for (int j = 0; j < 8; j++) {
        float lo, hi;
        unpack2(accA[j], lo, hi);
        *(ull*)(dA + 2 * j) = pack2(fmaxf(lo, 0.f), fmaxf(hi, 0.f));
        unpack2(accB[j], lo, hi);
        *(ull*)(dB + 2 * j) = pack2(fmaxf(lo, 0.f), fmaxf(hi, 0.f));
    }
}

// ---------------------------------------------------------------------------
// Kernel 2: fused MLP + projection, 32-obs tiles (R8-validated, frozen).
// Block 0 = query path (lastfeat inline, Wq -> g_q). Others: enc + kT.
// ---------------------------------------------------------------------------
__global__ __launch_bounds__(128) void k_mlp(
    const float* __restrict__ W0, const float* __restrict__ b0,
    const float* __restrict__ W1, const float* __restrict__ b1,
    const float* __restrict__ W2, const float* __restrict__ b2,
    const float* __restrict__ Wk, const float* __restrict__ bk,
    const float* __restrict__ Wq, const float* __restrict__ bq,
    int B)
{
    __shared__ __align__(16) float sf[NIN * ASTR];
    __shared__ __align__(16) float sA[HID * ASTR];
    __shared__ __align__(16) float sB[HID * ASTR];

    int tid = threadIdx.x;
    int r = tid & 63;
    int h = tid >> 6;

    bool special = (blockIdx.x == 0);
    int b = 0, l0 = 0, nv = 0;
    if (!special) {
        int bi = blockIdx.x - 1;
        b = bi >> 6;
        int lt = bi & 63;
        int len = g_lens[b];
        l0 = lt * 32;
        if (l0 >= len) return;
        nv = min(32, len - l0);
    } else {
        nv = min(B, 32);
    }

    for (int i = tid; i < HID * NIN; i += 128) {
        int o = i / NIN, k = i - o * NIN;
        sA[k * 129 + o] = __ldg(&W0[i]);
    }

    if (tid < 32) {
        int o = tid;
        float tv = 0.f, cv = 0.f, xv = 0.f;
        if (special) {
            int L = g_maxlen;
            if (o < nv && L >= 1 && g_lens[o] == L) {
                tv = g_St[o * LSTRIDE + L - 1];
                cv = g_Sc[o * LSTRIDE + L - 1];
                xv = g_Sx[o * LSTRIDE + L - 1];
            }
        } else if (o < nv) {
            tv = g_St[b * LSTRIDE + l0 + o];
            cv = g_Sc[b * LSTRIDE + l0 + o];
            xv = g_Sx[b * LSTRIDE + l0 + o];
        }
#pragma unroll
        for (int i = 0; i < 16; i++) {
            float ts = powf(100.0f, (float)i * (1.0f / 15.0f));
            float sn, cs;
            sincosf(tv / ts, &sn, &cs);
            sf[i * ASTR + o]        = sn;
            sf[(16 + i) * ASTR + o] = cs;
        }
        sf[32 * ASTR + o] = cv;
        sf[33 * ASTR + o] = xv;
    }
    __syncthreads();

    ull accA[8], accB[8];

    // ---- layer 0 ----
    {
        float bA = __ldg(&b0[r]);
        float bB = __ldg(&b0[r + 64]);
        ull iA = pack2(bA, bA), iB = pack2(bB, bB);
#pragma unroll
        for (int j = 0; j < 8; j++) { accA[j] = iA; accB[j] = iB; }
#pragma unroll 2
        for (int k = 0; k < NIN; k++) {
            float wA = sA[k * 129 + r];
            float wB = sA[k * 129 + 64 + r];
            ull wA2 = pack2(wA, wA), wB2 = pack2(wB, wB);
            const ulonglong2* row = (const ulonglong2*)(sf + k * ASTR + h * 16);
#pragma unroll
            for (int p = 0; p < 4; p++) {
                ulonglong2 v = row[p];
                accA[2 * p]     = ffma2(v.x, wA2, accA[2 * p]);
                accA[2 * p + 1] = ffma2(v.y, wA2, accA[2 * p + 1]);
                accB[2 * p]     = ffma2(v.x, wB2, accB[2 * p]);
                accB[2 * p + 1] = ffma2(v.y, wB2, accB[2 * p + 1]);
            }
        }
        __syncthreads();
        epi_relu(sA, accA, accB, r, h);
    }
    __syncthreads();

    // ---- layer 1 ----
    dense128(W1, b1, sA, sB, accA, accB, r, h, tid);
    epi_relu(sB, accA, accB, r, h);
    __syncthreads();

    // ---- layer 2 (enc) ----
    dense128(W2, b2, sB, sA, accA, accB, r, h, tid);
    {
        float vA[16], vB[16];
#pragma unroll
        for (int j = 0; j < 8; j++) {
            unpack2(accA[j], vA[2 * j], vA[2 * j + 1]);
            unpack2(accB[j], vB[2 * j], vB[2 * j + 1]);
        }
        float* dA = sA + r * ASTR + h * 16;
        float* dB = sA + (r + 64) * ASTR + h * 16;
#pragma unroll
        for (int j = 0; j < 8; j++) {
            *(ull*)(dA + 2 * j) = accA[j];
            *(ull*)(dB + 2 * j) = accB[j];
        }
        if (!special) {
#pragma unroll
            for (int o = 0; o < 16; o++) {
                int og = h * 16 + o;
                if (og < nv) {
                    size_t base = ((size_t)b * LSTRIDE + l0 + og) * HID;
                    g_enc[base + r]      = vA[o];
                    g_enc[base + 64 + r] = vB[o];
                }
            }
        }
    }
    __syncthreads();

    // ---- projection ----
    dense128(special ? Wq : Wk, special ? bq : bk, sA, sB, accA, accB, r, h, tid);
    {
        float vA[16], vB[16];
#pragma unroll
        for (int j = 0; j < 8; j++) {
            unpack2(accA[j], vA[2 * j], vA[2 * j + 1]);
            unpack2(accB[j], vB[2 * j], vB[2 * j + 1]);
        }
        if (special) {
#pragma unroll
            for (int o = 0; o < 16; o++) {
                int og = h * 16 + o;
                if (og < nv) {
                    g_q[og * HID + r]      = vA[o];
                    g_q[og * HID + 64 + r] = vB[o];
                }
            }
        } else {
            float* gkA = g_kT + ((size_t)b * HID + r) * LSTRIDE + l0 + h * 16;
            float* gkB = g_kT + ((size_t)b * HID + 64 + r) * LSTRIDE + l0 + h * 16;
#pragma unroll
            for (int o = 0; o < 16; o += 4) {
                int og = h * 16 + o;
                if (og + 4 <= nv) {
                    *(float4*)(gkA + o) = make_float4(vA[o], vA[o+1], vA[o+2], vA[o+3]);
                    *(float4*)(gkB + o) = make_float4(vB[o], vB[o+1], vB[o+2], vB[o+3]);
                } else {
                    for (int m = 0; m < 4; m++)
                        if (og + m < nv) { gkA[o + m] = vA[o + m]; gkB[o + m] = vB[o + m]; }
                }
            }
        }
    }
}

// ---------------------------------------------------------------------------
// Kernel 3: attention pass A with smem-staged tiles (validated R11, frozen).
// ---------------------------------------------------------------------------
__global__ __launch_bounds__(512) void k_attnA()
{
    int b = blockIdx.x, chunk = blockIdx.y, t = threadIdx.x;
    int len = min(g_lens[b], LSTRIDE);
    int l0 = chunk * CLEN;
    float* part = g_part + ((size_t)b * NCHUNK + chunk) * 512;

    if (l0 >= len) {
        part[t] = 0.f;
        if (t < 4) {
            g_cm  [(b * 4 + t) * NCHUNK + chunk] = -1e30f;
            g_csum[(b * 4 + t) * NCHUNK + chunk] = 0.f;
        }
        return;
    }

    extern __shared__ __align__(16) float dynA[];
    float* sq    = dynA;
    float* sbuf  = dynA + 128;
    float* sw4   = sbuf + 16512;
    float* sredw = sw4 + 512;
    float* smx   = sredw + 16;

    int nl = min(CLEN, len - l0);
    if (t < HID) sq[t] = g_q[b * HID + t];

    const float* kbase = g_kT + (size_t)b * HID * LSTRIDE + l0;
    for (int i = t; i < 4096; i += 512) {
        int e  = (i >> 3) & 127;
        int f4 = (i & 7) + ((i >> 10) << 3);
        float4 v = *(const float4*)(kbase + (size_t)e * LSTRIDE + f4 * 4);
        sbuf[(f4 * 4 + 0) * 129 + e] = v.x;
        sbuf[(f4 * 4 + 1) * 129 + e] = v.y;
        sbuf[(f4 * 4 + 2) * 129 + e] = v.z;
        sbuf[(f4 * 4 + 3) * 129 + e] = v.w;
    }
    __syncthreads();

    const float scale = 0.17677669529663687f;
    int l = t & 127, ha = t >> 7;
    int wid = t >> 5, lane = t & 31;

    float s = -1e30f;
    if (l < nl) {
        const float* kr = sbuf + l * 129 + ha * 32;
        const float* qr = sq + ha * 32;
        float a0 = 0.f, a1 = 0.f, a2 = 0.f, a3 = 0.f;
#pragma unroll
        for (int j = 0; j < 32; j += 4) {
            a0 = fmaf(kr[j],     qr[j],     a0);
            a1 = fmaf(kr[j + 1], qr[j + 1], a1);
            a2 = fmaf(kr[j + 2], qr[j + 2], a2);
            a3 = fmaf(kr[j + 3], qr[j + 3], a3);
        }
        s = ((a0 + a1) + (a2 + a3)) * scale;
    }

    {
        float v = s;
#pragma unroll
        for (int o = 16; o > 0; o >>= 1)
            v = fmaxf(v, __shfl_xor_sync(0xffffffffu, v, o));
        if (lane == 0) sredw[wid] = v;
    }
    __syncthreads();
    if (t < 4)
        smx[t] = fmaxf(fmaxf(sredw[t * 4], sredw[t * 4 + 1]),
                       fmaxf(sredw[t * 4 + 2], sredw[t * 4 + 3]));
    __syncthreads();

    float wv = (l < nl) ? expf(s - smx[ha]) : 0.f;
    sw4[l * 4 + ha] = wv;
    {
        float v = wv;
#pragma unroll
        for (int o = 16; o > 0; o >>= 1)
            v += __shfl_xor_sync(0xffffffffu, v, o);
        if (lane == 0) sredw[wid] = v;
    }
    __syncthreads();
    if (t < 4) {
        g_cm  [(b * 4 + t) * NCHUNK + chunk] = smx[t];
        g_csum[(b * 4 + t) * NCHUNK + chunk] =
            (sredw[t * 4] + sredw[t * 4 + 1]) + (sredw[t * 4 + 2] + sredw[t * 4 + 3]);
    }
    __syncthreads();

    const float* ebase = g_enc + ((size_t)b * LSTRIDE + l0) * HID;
    for (int i = t; i < 4096; i += 512)
        *(float4*)(sbuf + i * 4) = *(const float4*)(ebase + i * 4);
    __syncthreads();

    int ls = t >> 7, e = t & 127;
    float ac0 = 0.f, ac1 = 0.f, ac2 = 0.f, ac3 = 0.f;
    int lstart = ls * 32;
#pragma unroll 8
    for (int li = 0; li < 32; li++) {
        int ll = lstart + li;
        float ev = sbuf[ll * 128 + e];
        float4 w4 = *(const float4*)(sw4 + ll * 4);
        ac0 = fmaf(ev, w4.x, ac0);
        ac1 = fmaf(ev, w4.y, ac1);
        ac2 = fmaf(ev, w4.z, ac2);
        ac3 = fmaf(ev, w4.w, ac3);
    }
    __syncthreads();
    *(float4*)(sbuf + ((ls * 128 + e) << 2)) = make_float4(ac0, ac1, ac2, ac3);
    __syncthreads();

    {
        int ha2 = t >> 7, e2 = t & 127;
        float rr = 0.f;
#pragma unroll
        for (int q = 0; q < 4; q++)
            rr += sbuf[((q * 128 + e2) << 2) + ha2];
        part[t] = rr;
    }
}

// ---------------------------------------------------------------------------
// Kernel 4: rescale-combine. grid B*4, 128 threads (one block per (b,h)).
// ---------------------------------------------------------------------------
__global__ __launch_bounds__(128) void k_attnB(float* __restrict__ out)
{
    int bh = blockIdx.x;
    int b = bh >> 2, h = bh & 3;
    int t = threadIdx.x;

    float m = -1e30f;
#pragma unroll
    for (int c = 0; c < NCHUNK; c++) m = fmaxf(m, g_cm[bh * NCHUNK + c]);

    float denom = 0.f, num = 0.f;
#pragma unroll
    for (int c = 0; c < NCHUNK; c++) {
        float f = expf(g_cm[bh * NCHUNK + c] - m);
        denom = fmaf(g_csum[bh * NCHUNK + c], f, denom);
        num   = fmaf(g_part[((size_t)b * NCHUNK + c) * 512 + h * 128 + t], f, num);
    }
    out[b * 512 + h * 128 + t] = num / denom;
}

// ---------------------------------------------------------------------------
extern "C" void kernel_launch(void* const* d_in, const int* in_sizes, int n_in,
                              void* d_out, int out_size)
{
    const float* times    = (const float*)d_in[0];
    const int*   time_ptr = (const int*)  d_in[1];
    const float* X        = (const float*)d_in[2];
    const int*   M        = (const int*)  d_in[3];
    const float* W0 = (const float*)d_in[6];
    const float* b0 = (const float*)d_in[7];
    const float* W1 = (const float*)d_in[8];
    const float* b1 = (const float*)d_in[9];
    const float* W2 = (const float*)d_in[10];
    const float* b2 = (const float*)d_in[11];
    const float* Wq = (const float*)d_in[12];
    const float* bq = (const float*)d_in[13];
    const float* Wk = (const float*)d_in[14];
    const float* bk = (const float*)d_in[15];

    int R       = in_sizes[0];
    int n_times = in_sizes[0];
    int V       = in_sizes[2] / R;
    int B       = in_sizes[5];

    const int ATTN_SMEM = (128 + 128 * 129 + 512 + 16 + 4) * (int)sizeof(float);
    cudaFuncSetAttribute(k_attnA, cudaFuncAttributeMaxDynamicSharedMemorySize,
                         ATTN_SMEM);

    k_compact<<<B, 256>>>(times, time_ptr, X, M, R, V, B, n_times);
    k_mlp<<<B * 64 + 1, 128>>>(W0, b0, W1, b1, W2, b2, Wk, bk, Wq, bq, B);
    dim3 gs(B, NCHUNK);
    k_attnA<<<gs, 512, ATTN_SMEM>>>();
    k_attnB<<<B * 4, 128>>>((float*)d_out);
}